// round 1
// baseline (speedup 1.0000x reference)
#include <cuda_runtime.h>
#include <math.h>

// FNO spectral conv, truncated separable DFTs.
// B=8, H=W=256, CIN=COUT=32, M1=M2=16.
#define NB 8
#define NH 256
#define NW 256
#define NC 32
#define KX 16

// Scratch (device globals; no runtime allocation).
__device__ __align__(16) float2 g_T[NB * KX * NH * NC];   // [b][kx][h][c]    8 MB
__device__ __align__(16) float2 g_X[32 * KX * NB * NC];   // [p][kx][b][ci]   1 MB  (p = blk*16+m1)
__device__ __align__(16) float2 g_Y[NB * NC * 32 * KX];   // [b][co][p][kx]   1 MB
__device__ __align__(16) float2 g_G[NB * NH * KX * NC];   // [b][h][kx][co]   8 MB

// ---------------------------------------------------------------------------
// K1: forward DFT over w.  T[b,kx,h,c] = sum_w x[b,h,w,c] * e^{-2pi i kx w/256}
// grid: 2048 (b*256+h), 128 threads. Each thread: kx pair x c pair (4 outputs).
// ---------------------------------------------------------------------------
__global__ __launch_bounds__(128) void k1_dft_w(const float* __restrict__ x) {
    __shared__ __align__(16) float sx[NW * NC];   // 32 KB: [w][c]
    __shared__ __align__(16) float2 tab[256];     // e^{+2pi i n/256} = (cos, sin)
    const int t = threadIdx.x;
    const int blk = blockIdx.x;                   // b*256 + h

    for (int i = t; i < 256; i += 128) {
        float s, c;
        sincospif((float)i * (1.0f / 128.0f), &s, &c);
        tab[i] = make_float2(c, s);
    }
    {
        const float4* xp = (const float4*)(x + (size_t)blk * (NW * NC));
        float4* sxp = (float4*)sx;
        for (int i = t; i < (NW * NC) / 4; i += 128) sxp[i] = xp[i];
    }
    __syncthreads();

    const int p = t >> 4;        // 0..7
    const int q = t & 15;        // 0..15
    const int kx0 = 2 * p, kx1 = 2 * p + 1;
    const int c0 = 2 * q;

    float2 a00 = {0.f, 0.f}, a01 = {0.f, 0.f}, a10 = {0.f, 0.f}, a11 = {0.f, 0.f};
    int ia = 0, ib = 0;
#pragma unroll 4
    for (int w = 0; w < 256; w++) {
        const float2 xv = *(const float2*)&sx[w * NC + c0];
        const float2 t0 = tab[ia];
        const float2 t1 = tab[ib];
        ia = (ia + kx0) & 255;
        ib = (ib + kx1) & 255;
        // e^{-i theta}: re += x*cos, im -= x*sin
        a00.x += xv.x * t0.x; a00.y -= xv.x * t0.y;
        a01.x += xv.y * t0.x; a01.y -= xv.y * t0.y;
        a10.x += xv.x * t1.x; a10.y -= xv.x * t1.y;
        a11.x += xv.y * t1.x; a11.y -= xv.y * t1.y;
    }

    const int b = blk >> 8, h = blk & 255;
    float4* T4 = (float4*)g_T;
    T4[((((b * 16 + kx0) * 256 + h) * 32 + c0) >> 1)] = make_float4(a00.x, a00.y, a01.x, a01.y);
    T4[((((b * 16 + kx1) * 256 + h) * 32 + c0) >> 1)] = make_float4(a10.x, a10.y, a11.x, a11.y);
}

// ---------------------------------------------------------------------------
// K2: forward DFT over h for the 32 kept ky modes.
// X[p,kx,b,c] = sum_h T[b,kx,h,c] * e^{-2pi i f h/256},  f = p (p<16) or p-16 for
// the high block (thread's second output p+16 -> f = p-16).
// grid: (16 kx, 2 cHalf, 8 b), 256 threads.
// ---------------------------------------------------------------------------
__global__ __launch_bounds__(256) void k2_dft_h() {
    __shared__ __align__(16) float2 sT[256 * 16];  // 32 KB: [h][cl]
    __shared__ __align__(16) float2 tab[256];
    const int t = threadIdx.x;
    const int kx = blockIdx.x, ch = blockIdx.y, b = blockIdx.z;

    {
        float s, c;
        sincospif((float)t * (1.0f / 128.0f), &s, &c);
        tab[t] = make_float2(c, s);
    }
    {
        const float2* src = g_T + (size_t)((b * 16 + kx) * 256) * 32 + ch * 16;
        for (int i = t; i < 4096; i += 256) {
            const int h = i >> 4, cl = i & 15;
            sT[i] = src[h * 32 + cl];
        }
    }
    __syncthreads();

    const int p = t >> 4;   // 0..15
    const int q = t & 15;   // 0..15 (local c)
    float2 Xa = {0.f, 0.f}, Xb = {0.f, 0.f};
    int ia = 0, ib = 0;
    const int inca = p;                 // f = p
    const int incb = (p + 240) & 255;   // f = p-16 (mod 256)
#pragma unroll 4
    for (int h = 0; h < 256; h++) {
        const float2 Tv = sT[h * 16 + q];
        const float2 ta = tab[ia];
        const float2 tb = tab[ib];
        ia = (ia + inca) & 255;
        ib = (ib + incb) & 255;
        // T * e^{-i theta} = (Tr c + Ti s) + i (Ti c - Tr s)
        Xa.x += Tv.x * ta.x + Tv.y * ta.y; Xa.y += Tv.y * ta.x - Tv.x * ta.y;
        Xb.x += Tv.x * tb.x + Tv.y * tb.y; Xb.y += Tv.y * tb.x - Tv.x * tb.y;
    }
    const int c = ch * 16 + q;
    g_X[(p * 16 + kx) * 256 + b * 32 + c]        = Xa;
    g_X[((p + 16) * 16 + kx) * 256 + b * 32 + c] = Xb;
}

// ---------------------------------------------------------------------------
// K3: channel mixing. Y[b,co,p,kx] = sum_ci X[p,kx,b,ci] * W[blk,ci,co,m1,kx]
// grid: (16 kx, 32 p), 256 threads (one (b,co) per thread).
// ---------------------------------------------------------------------------
__global__ __launch_bounds__(256) void k3_mix(const float* __restrict__ wr,
                                              const float* __restrict__ wi) {
    __shared__ __align__(16) float2 sX[256];     // [b][ci]
    __shared__ float swr[1024], swi[1024];       // [ci][co]
    const int t = threadIdx.x;
    const int kx = blockIdx.x, p = blockIdx.y;

    sX[t] = g_X[(p * 16 + kx) * 256 + t];
    const int blk = p >> 4, m1 = p & 15;
    const float* wrb = wr + blk * 262144 + m1 * 16 + kx;
    const float* wib = wi + blk * 262144 + m1 * 16 + kx;
    for (int i = t; i < 1024; i += 256) {
        const int ci = i >> 5, co = i & 31;
        swr[i] = wrb[ci * 8192 + co * 256];
        swi[i] = wib[ci * 8192 + co * 256];
    }
    __syncthreads();

    const int b = t >> 5, co = t & 31;
    float2 acc = {0.f, 0.f};
#pragma unroll
    for (int ci = 0; ci < 32; ci++) {
        const float2 Xv = sX[b * 32 + ci];
        const float Wr = swr[ci * 32 + co];
        const float Wi = swi[ci * 32 + co];
        acc.x += Xv.x * Wr - Xv.y * Wi;
        acc.y += Xv.x * Wi + Xv.y * Wr;
    }
    g_Y[((b * 32 + co) * 32 + p) * 16 + kx] = acc;
}

// ---------------------------------------------------------------------------
// K4: inverse DFT over h. G[b,h,kx,co] = s_kx * sum_p Y[b,co,p,kx] e^{+2pi i f h/256}
// with f = p (p<16) else p-32; s_kx = (kx==0 ? 1 : 2)/65536.
// grid: (4 hChunk, 4 coChunk, 8 b), 256 threads; each thread 2 (h,co) pairs.
// ---------------------------------------------------------------------------
__global__ __launch_bounds__(256) void k4_idft_h() {
    __shared__ __align__(16) float2 sY[512 * 9];  // [(p*16+kx)][col], padded stride 9 (36 KB)
    __shared__ __align__(16) float2 tab[256];
    const int t = threadIdx.x;
    const int hc = blockIdx.x, cc = blockIdx.y, b = blockIdx.z;

    {
        float s, c;
        sincospif((float)t * (1.0f / 128.0f), &s, &c);
        tab[t] = make_float2(c, s);
    }
    for (int i = t; i < 4096; i += 256) {
        const int col = i >> 9, pk = i & 511;
        sY[pk * 9 + col] = g_Y[(size_t)(b * 32 + cc * 8 + col) * 512 + pk];
    }
    __syncthreads();

#pragma unroll
    for (int j = 0; j < 2; j++) {
        const int P = t + j * 256;
        const int hl = P >> 3, col = P & 7;
        const int h = hc * 64 + hl;
        float2 acc[16];
#pragma unroll
        for (int kx = 0; kx < 16; kx++) acc[kx] = make_float2(0.f, 0.f);

        const int incr = h & 255;
        int m = 0;                       // p = 0..15: f = p, m = (p*h) mod 256
        for (int p = 0; p < 16; p++) {
            const float2 tw = tab[m];
            m = (m + incr) & 255;
#pragma unroll
            for (int kx = 0; kx < 16; kx++) {
                const float2 Yv = sY[(p * 16 + kx) * 9 + col];
                acc[kx].x += Yv.x * tw.x - Yv.y * tw.y;
                acc[kx].y += Yv.x * tw.y + Yv.y * tw.x;
            }
        }
        m = (-16 * h) & 255;             // p = 16..31: f = p-32
        for (int p = 16; p < 32; p++) {
            const float2 tw = tab[m];
            m = (m + incr) & 255;
#pragma unroll
            for (int kx = 0; kx < 16; kx++) {
                const float2 Yv = sY[(p * 16 + kx) * 9 + col];
                acc[kx].x += Yv.x * tw.x - Yv.y * tw.y;
                acc[kx].y += Yv.x * tw.y + Yv.y * tw.x;
            }
        }
        const int co = cc * 8 + col;
#pragma unroll
        for (int kx = 0; kx < 16; kx++) {
            const float s = (kx == 0 ? 1.0f : 2.0f) * (1.0f / 65536.0f);
            g_G[((size_t)(b * 256 + h) * 16 + kx) * 32 + co] =
                make_float2(acc[kx].x * s, acc[kx].y * s);
        }
    }
}

// ---------------------------------------------------------------------------
// K5: inverse DFT over w + channels-last store.
// out[b,h,w,co] = sum_kx ( Gr[kx]*cos(2pi kx w/256) - Gi[kx]*sin(...) )
// grid: 2048 (b*256+h), 256 threads; thread = (warp -> w stride 8, lane -> co).
// ---------------------------------------------------------------------------
__global__ __launch_bounds__(256) void k5_idft_w(float* __restrict__ out) {
    __shared__ __align__(16) float stw[256 * 32];  // [w][kx]{cos,sin}, 32 KB
    __shared__ __align__(16) float2 tab[256];
    const int t = threadIdx.x;
    const int blk = blockIdx.x;   // b*256 + h

    {
        float s, c;
        sincospif((float)t * (1.0f / 128.0f), &s, &c);
        tab[t] = make_float2(c, s);
    }
    __syncthreads();
    {
        const int w = t;
        int m = 0;
#pragma unroll
        for (int kx = 0; kx < 16; kx++) {
            const float2 tw = tab[m];
            m = (m + w) & 255;
            stw[w * 32 + 2 * kx]     = tw.x;
            stw[w * 32 + 2 * kx + 1] = tw.y;
        }
    }
    const int co = t & 31;
    float gr[16], gi[16];
    {
        const float2* Gp = g_G + (size_t)blk * (16 * 32) + co;
#pragma unroll
        for (int kx = 0; kx < 16; kx++) {
            const float2 v = Gp[kx * 32];
            gr[kx] = v.x;
            gi[kx] = v.y;
        }
    }
    __syncthreads();

    const int ws = t >> 5;
    float* outp = out + (size_t)blk * (NW * NC) + co;
#pragma unroll 2
    for (int j = 0; j < 32; j++) {
        const int w = j * 8 + ws;
        const float4* tw4 = (const float4*)&stw[w * 32];
        float acc = 0.f;
#pragma unroll
        for (int k2 = 0; k2 < 8; k2++) {
            const float4 v = tw4[k2];
            acc += gr[2 * k2]     * v.x;
            acc -= gi[2 * k2]     * v.y;
            acc += gr[2 * k2 + 1] * v.z;
            acc -= gi[2 * k2 + 1] * v.w;
        }
        outp[w * 32] = acc;
    }
}

// ---------------------------------------------------------------------------
extern "C" void kernel_launch(void* const* d_in, const int* in_sizes, int n_in,
                              void* d_out, int out_size) {
    (void)n_in; (void)out_size; (void)in_sizes;
    const float* x  = (const float*)d_in[0];
    const float* wr = (const float*)d_in[1];
    const float* wi = (const float*)d_in[2];
    float* out = (float*)d_out;

    k1_dft_w<<<NB * NH, 128>>>(x);
    k2_dft_h<<<dim3(16, 2, 8), 256>>>();
    k3_mix<<<dim3(16, 32), 256>>>(wr, wi);
    k4_idft_h<<<dim3(4, 4, 8), 256>>>();
    k5_idft_w<<<NB * NH, 256>>>(out);
}